// round 14
// baseline (speedup 1.0000x reference)
#include <cuda_runtime.h>
#include <cuda_bf16.h>
#include <cuda_fp16.h>
#include <mma.h>
#include <stdint.h>
#include <math.h>

using namespace nvcuda;

#define NMAX 50048   // 391 * 128, WMMA tile stores never OOB
#define EMAX 1000000

__device__ __nv_bfloat16 g_Wbf[3][2][256*128]; // [layer][hi/lo][c][k]
__device__ __half g_m[NMAX*128];               // fp16 messages
__device__ float  g_u[NMAX*128];
__device__ __nv_bfloat16 g_hH[NMAX*128];       // h (or x) hi part
__device__ __nv_bfloat16 g_hL[NMAX*128];       // h (or x) lo part
__device__ float  g_scr[NMAX*32];
__device__ int    g_is64;
__device__ int    g_cnt[NMAX];
__device__ int    g_off[NMAX + 1];
__device__ int    g_cur[NMAX];
__device__ int    g_src_sorted[EMAX];
__device__ float  g_w_sorted[EMAX];

// ================= prep: weights + x -> bf16 hi/lo =================
__global__ void prep_kernel(const float* __restrict__ Wm0, const float* __restrict__ Wu0,
                            const float* __restrict__ Wm1, const float* __restrict__ Wu1,
                            const float* __restrict__ Wm2, const float* __restrict__ Wu2,
                            const float* __restrict__ x, int N) {
    int idx = blockIdx.x * blockDim.x + threadIdx.x;
    const int wt = 3 * 256 * 128;
    for (int t = idx; t < wt; t += gridDim.x * blockDim.x) {
        int l = t / (256 * 128);
        int r = t % (256 * 128);
        int c = r / 128;
        int k = r % 128;
        const float* W;
        if (c < 128) W = (l == 0) ? Wm0 : (l == 1) ? Wm1 : Wm2;
        else         W = (l == 0) ? Wu0 : (l == 1) ? Wu1 : Wu2;
        float v = W[(c & 127) * 128 + k];
        __nv_bfloat16 hi = __float2bfloat16(v);
        __nv_bfloat16 lo = __float2bfloat16(v - __bfloat162float(hi));
        g_Wbf[l][0][c * 128 + k] = hi;
        g_Wbf[l][1][c * 128 + k] = lo;
    }
    int xt = N * 128 / 4;
    for (int t = idx; t < xt; t += gridDim.x * blockDim.x) {
        float4 v = ((const float4*)x)[t];
        union { unsigned short u[4]; uint2 q; } H, L;
        float vv[4] = {v.x, v.y, v.z, v.w};
        #pragma unroll
        for (int j = 0; j < 4; j++) {
            __nv_bfloat16 hv = __float2bfloat16(vv[j]);
            __nv_bfloat16 lv = __float2bfloat16(vv[j] - __bfloat162float(hv));
            H.u[j] = __bfloat16_as_ushort(hv);
            L.u[j] = __bfloat16_as_ushort(lv);
        }
        ((uint2*)g_hH)[t] = H.q;
        ((uint2*)g_hL)[t] = L.q;
    }
}

// ================= CSR build (forked stream) =================
__global__ void zero_kernel(const void* __restrict__ ei, int N) {
    int idx = blockIdx.x * blockDim.x + threadIdx.x;
    if (idx == 0) {
        const int* p = (const int*)ei;
        int is64 = 1;
        for (int i = 0; i < 32; i++) if (p[2*i + 1] != 0) { is64 = 0; break; }
        g_is64 = is64;
    }
    for (int t = idx; t < N; t += gridDim.x * blockDim.x) g_cnt[t] = 0;
}

__global__ void hist_kernel(const void* __restrict__ ei, int E) {
    int i = blockIdx.x * blockDim.x + threadIdx.x;
    if (i >= E) return;
    int dst = g_is64 ? (int)((const long long*)ei)[E + i] : ((const int*)ei)[E + i];
    atomicAdd(&g_cnt[dst], 1);
}

__global__ __launch_bounds__(1024) void scan_kernel(int N) {
    __shared__ int part[1024];
    int t = threadIdx.x;
    int chunk = (N + 1023) / 1024;
    int b = t * chunk;
    int e = min(b + chunk, N);
    int s = 0;
    for (int i = b; i < e; i++) s += g_cnt[i];
    part[t] = s;
    __syncthreads();
    for (int d = 1; d < 1024; d <<= 1) {
        int v = (t >= d) ? part[t - d] : 0;
        __syncthreads();
        part[t] += v;
        __syncthreads();
    }
    int run = (t == 0) ? 0 : part[t - 1];
    for (int i = b; i < e; i++) {
        int c = g_cnt[i];
        g_off[i] = run;
        g_cur[i] = run;
        run += c;
    }
    if (e == N && b <= N) g_off[N] = run;
}

__global__ void scatter_kernel(const void* __restrict__ ei, const float* __restrict__ ew, int E) {
    int i = blockIdx.x * blockDim.x + threadIdx.x;
    if (i >= E) return;
    int src, dst;
    if (g_is64) {
        const long long* p = (const long long*)ei;
        src = (int)p[i]; dst = (int)p[E + i];
    } else {
        const int* p = (const int*)ei;
        src = p[i]; dst = p[E + i];
    }
    int pos = atomicAdd(&g_cur[dst], 1);
    g_src_sorted[pos] = src;
    g_w_sorted[pos]   = ew[i];
}

// ================= WMMA dual GEMM: 512 threads, 8 row-groups x 2 col-groups =================
#define LDP 136
#define XS_H 0
#define XS_L (128*LDP*2)
#define WS_H (2*128*LDP*2)
#define WS_L (WS_H + 256*LDP*2)
#define G_EPI (WS_L + 256*LDP*2)
#define GEMM_SMEM (G_EPI + 16*256*4)

__global__ __launch_bounds__(512, 1) void dual_gemm_wmma(
    const __nv_bfloat16* __restrict__ aHg, const __nv_bfloat16* __restrict__ aLg,
    const __nv_bfloat16* __restrict__ Whi, const __nv_bfloat16* __restrict__ Wlo,
    __half* __restrict__ outm, float* __restrict__ outu, int N)
{
    extern __shared__ char sm[];
    __nv_bfloat16* xsH = (__nv_bfloat16*)(sm + XS_H);
    __nv_bfloat16* xsL = (__nv_bfloat16*)(sm + XS_L);
    __nv_bfloat16* wsH = (__nv_bfloat16*)(sm + WS_H);
    __nv_bfloat16* wsL = (__nv_bfloat16*)(sm + WS_L);
    int tid = threadIdx.x, warp = tid >> 5, lane = tid & 31;
    float* ep = (float*)(sm + G_EPI) + warp * 256;

    int rg = warp >> 1;          // row group 0..7 -> rows rg*16
    int cg = warp & 1;           // 0 -> m cols [0,128), 1 -> u cols [128,256)

    for (int i = tid; i < 256 * 16; i += 512) {
        int r = i >> 4, ch = i & 15;
        ((uint4*)(wsH + r * LDP))[ch] = ((const uint4*)(Whi + r * 128))[ch];
        ((uint4*)(wsL + r * LDP))[ch] = ((const uint4*)(Wlo + r * 128))[ch];
    }

    int ntiles = (N + 127) >> 7;

    for (int tile = blockIdx.x; tile < ntiles; tile += gridDim.x) {
        int row0 = tile << 7;
        __syncthreads();
        for (int i = tid; i < 2048; i += 512) {
            int r = i >> 4, ch = i & 15;
            size_t g = (size_t)(row0 + r) * 128;
            ((uint4*)(xsH + r * LDP))[ch] = ((const uint4*)(aHg + g))[ch];
            ((uint4*)(xsL + r * LDP))[ch] = ((const uint4*)(aLg + g))[ch];
        }
        __syncthreads();

        wmma::fragment<wmma::accumulator, 16, 16, 16, float> acc[8];
        #pragma unroll
        for (int f = 0; f < 8; f++) wmma::fill_fragment(acc[f], 0.0f);

        #pragma unroll
        for (int pass = 0; pass < 3; pass++) {
            const __nv_bfloat16* A = (pass == 2) ? xsL : xsH;
            const __nv_bfloat16* B = (pass == 1) ? wsL : wsH;
            #pragma unroll
            for (int k = 0; k < 8; k++) {
                wmma::fragment<wmma::matrix_a, 16, 16, 16, __nv_bfloat16, wmma::row_major> af;
                wmma::load_matrix_sync(af, A + (rg * 16) * LDP + k * 16, LDP);
                #pragma unroll
                for (int f = 0; f < 8; f++) {
                    wmma::fragment<wmma::matrix_b, 16, 16, 16, __nv_bfloat16, wmma::col_major> bf;
                    wmma::load_matrix_sync(bf, B + (cg * 128 + f * 16) * LDP + k * 16, LDP);
                    wmma::mma_sync(acc[f], af, bf, acc[f]);
                }
            }
        }

        int gr0 = row0 + rg * 16;   // padded buffers, never OOB
        if (cg == 0) {
            // m half: stage fp32 fragment, convert to fp16, vector-store
            #pragma unroll
            for (int f = 0; f < 8; f++) {
                wmma::store_matrix_sync(ep, acc[f], 16, wmma::mem_row_major);
                __syncwarp();
                int row = lane >> 1, c0 = (lane & 1) * 8;
                const float* s = ep + row * 16 + c0;
                union { __half h[8]; uint4 q; } o;
                #pragma unroll
                for (int j = 0; j < 8; j++) o.h[j] = __float2half_rn(s[j]);
                *(uint4*)(outm + (size_t)(gr0 + row) * 128 + f * 16 + c0) = o.q;
                __syncwarp();
            }
        } else {
            #pragma unroll
            for (int f = 0; f < 8; f++)
                wmma::store_matrix_sync(outu + (size_t)gr0 * 128 + f * 16,
                                        acc[f], 128, wmma::mem_row_major);
        }
    }
}

// ================= fused CSR aggregate (fp16 gather, 8-edge unroll) + bias + fast tanh =================
__device__ __forceinline__ float fast_tanh(float x) {
    float e = __expf(2.0f * x);
    return 1.0f - 2.0f / (e + 1.0f);
}

__global__ __launch_bounds__(256) void agg_tanh(
    const __half* __restrict__ m, const float* __restrict__ u,
    const float* __restrict__ bu,
    __nv_bfloat16* __restrict__ hH, __nv_bfloat16* __restrict__ hL, int N)
{
    int node = (blockIdx.x * blockDim.x + threadIdx.x) >> 5;
    int lane = threadIdx.x & 31;
    if (node >= N) return;
    int b = g_off[node], e = g_off[node + 1];

    float4 bb = *(const float4*)(bu + lane*4);
    float4 uu = *(const float4*)(u + (size_t)node*128 + lane*4);
    float4 acc = make_float4(uu.x + bb.x, uu.y + bb.y, uu.z + bb.z, uu.w + bb.w);

    int i = b;
    for (; i + 8 <= e; i += 8) {
        int   s[8];
        float w[8];
        #pragma unroll
        for (int j = 0; j < 8; j++) { s[j] = g_src_sorted[i + j]; w[j] = g_w_sorted[i + j]; }
        uint2 r[8];
        #pragma unroll
        for (int j = 0; j < 8; j++) r[j] = *(const uint2*)(m + (size_t)s[j]*128 + lane*4);
        #pragma unroll
        for (int j = 0; j < 8; j++) {
            float2 a = __half22float2(*(__half2*)&r[j].x);
            float2 c = __half22float2(*(__half2*)&r[j].y);
            acc.x = fmaf(w[j], a.x, acc.x);
            acc.y = fmaf(w[j], a.y, acc.y);
            acc.z = fmaf(w[j], c.x, acc.z);
            acc.w = fmaf(w[j], c.y, acc.w);
        }
    }
    for (; i < e; i++) {
        int   s = g_src_sorted[i];
        float w = g_w_sorted[i];
        uint2 r = *(const uint2*)(m + (size_t)s*128 + lane*4);
        float2 a = __half22float2(*(__half2*)&r.x), c = __half22float2(*(__half2*)&r.y);
        acc.x = fmaf(w, a.x, acc.x);
        acc.y = fmaf(w, a.y, acc.y);
        acc.z = fmaf(w, c.x, acc.z);
        acc.w = fmaf(w, c.y, acc.w);
    }
    float v[4] = {fast_tanh(acc.x), fast_tanh(acc.y), fast_tanh(acc.z), fast_tanh(acc.w)};
    union { unsigned short us[4]; uint2 q; } H, L;
    #pragma unroll
    for (int j = 0; j < 4; j++) {
        __nv_bfloat16 hv = __float2bfloat16(v[j]);
        __nv_bfloat16 lv = __float2bfloat16(v[j] - __bfloat162float(hv));
        H.us[j] = __bfloat16_as_ushort(hv);
        L.us[j] = __bfloat16_as_ushort(lv);
    }
    *(uint2*)(hH + (size_t)node*128 + lane*4) = H.q;
    *(uint2*)(hL + (size_t)node*128 + lane*4) = L.q;
}

// ================= WMMA output GEMM: out = h @ Wout.T + bout (C=32) =================
#define OLDP 136
#define OA_H 0
#define OA_L (128*OLDP*2)
#define OW_H (2*128*OLDP*2)
#define OW_L (OW_H + 32*OLDP*2)
#define OBIAS (OW_L + 32*OLDP*2)
#define OUT_SMEM (OBIAS + 16*40*4)

__global__ __launch_bounds__(256, 1) void out_gemm_wmma(
    const __nv_bfloat16* __restrict__ aHg, const __nv_bfloat16* __restrict__ aLg,
    const float* __restrict__ Wout,
    const float* __restrict__ bout, float* __restrict__ out,
    float* __restrict__ scratch, int N)
{
    extern __shared__ char sm[];
    __nv_bfloat16* aH = (__nv_bfloat16*)(sm + OA_H);
    __nv_bfloat16* aL = (__nv_bfloat16*)(sm + OA_L);
    __nv_bfloat16* wH = (__nv_bfloat16*)(sm + OW_H);
    __nv_bfloat16* wL = (__nv_bfloat16*)(sm + OW_L);
    float* bs = (float*)(sm + OBIAS);
    int tid = threadIdx.x, warp = tid >> 5, lane = tid & 31;

    for (int i = tid; i < 32 * 16; i += 256) {
        int r = i >> 4, ch = i & 15;
        float4 a = *(const float4*)(Wout + r * 128 + ch * 8);
        float4 b = *(const float4*)(Wout + r * 128 + ch * 8 + 4);
        float v[8] = {a.x, a.y, a.z, a.w, b.x, b.y, b.z, b.w};
        union { unsigned short u[8]; uint4 q; } H, L;
        #pragma unroll
        for (int j = 0; j < 8; j++) {
            __nv_bfloat16 hv = __float2bfloat16(v[j]);
            __nv_bfloat16 lv = __float2bfloat16(v[j] - __bfloat162float(hv));
            H.u[j] = __bfloat16_as_ushort(hv);
            L.u[j] = __bfloat16_as_ushort(lv);
        }
        *(uint4*)(wH + r * OLDP + ch * 8) = H.q;
        *(uint4*)(wL + r * OLDP + ch * 8) = L.q;
    }
    for (int i = tid; i < 16 * 40; i += 256) {
        int c = i % 40;
        bs[i] = (c < 32) ? bout[c] : 0.f;
    }

    int ntiles = (N + 127) >> 7;
    for (int tile = blockIdx.x; tile < ntiles; tile += gridDim.x) {
        int row0 = tile << 7;
        __syncthreads();
        for (int i = tid; i < 2048; i += 256) {
            int r = i >> 4, ch = i & 15;
            size_t g = (size_t)(row0 + r) * 128;
            ((uint4*)(aH + r * OLDP))[ch] = ((const uint4*)(aHg + g))[ch];
            ((uint4*)(aL + r * OLDP))[ch] = ((const uint4*)(aLg + g))[ch];
        }
        __syncthreads();

        wmma::fragment<wmma::accumulator, 16, 16, 16, float> acc[2];
        #pragma unroll
        for (int f = 0; f < 2; f++)
            wmma::load_matrix_sync(acc[f], bs + f * 16, 40, wmma::mem_row_major);

        #pragma unroll
        for (int pass = 0; pass < 3; pass++) {
            const __nv_bfloat16* A = (pass == 2) ? aL : aH;
            const __nv_bfloat16* B = (pass == 1) ? wL : wH;
            #pragma unroll
            for (int k = 0; k < 8; k++) {
                wmma::fragment<wmma::matrix_a, 16, 16, 16, __nv_bfloat16, wmma::row_major> af;
                wmma::load_matrix_sync(af, A + (warp * 16) * OLDP + k * 16, OLDP);
                #pragma unroll
                for (int f = 0; f < 2; f++) {
                    wmma::fragment<wmma::matrix_b, 16, 16, 16, __nv_bfloat16, wmma::col_major> bf;
                    wmma::load_matrix_sync(bf, B + (f * 16) * OLDP + k * 16, OLDP);
                    wmma::mma_sync(acc[f], af, bf, acc[f]);
                }
            }
        }
        int gr0 = row0 + warp * 16;
        if (gr0 + 16 <= N) {
            wmma::store_matrix_sync(out + (size_t)gr0 * 32,      acc[0], 32, wmma::mem_row_major);
            wmma::store_matrix_sync(out + (size_t)gr0 * 32 + 16, acc[1], 32, wmma::mem_row_major);
        } else if (gr0 < N) {
            float* sc = scratch + (size_t)gr0 * 32;
            wmma::store_matrix_sync(sc,      acc[0], 32, wmma::mem_row_major);
            wmma::store_matrix_sync(sc + 16, acc[1], 32, wmma::mem_row_major);
            __syncwarp();
            for (int r = 0; r < 16; r++) {
                int gr = gr0 + r;
                if (gr < N) out[(size_t)gr * 32 + lane] = sc[r * 32 + lane];
            }
        }
    }
}

extern "C" void kernel_launch(void* const* d_in, const int* in_sizes, int n_in,
                              void* d_out, int out_size) {
    const float* x    = (const float*)d_in[0];
    const void*  ei   = d_in[1];
    const float* ew   = (const float*)d_in[2];
    const float* Wm0  = (const float*)d_in[3];
    const float* Wu0  = (const float*)d_in[4];
    const float* bu0  = (const float*)d_in[5];
    const float* Wm1  = (const float*)d_in[6];
    const float* Wu1  = (const float*)d_in[7];
    const float* bu1  = (const float*)d_in[8];
    const float* Wm2  = (const float*)d_in[9];
    const float* Wu2  = (const float*)d_in[10];
    const float* bu2  = (const float*)d_in[11];
    const float* Wout = (const float*)d_in[12];
    const float* bout = (const float*)d_in[13];
    float* out = (float*)d_out;

    int N = in_sizes[0] / 128;
    int E = in_sizes[2];

    __nv_bfloat16 *pW, *phH, *phL;
    __half* pm;
    float *pu, *psc;
    cudaGetSymbolAddress((void**)&pW,  g_Wbf);
    cudaGetSymbolAddress((void**)&pm,  g_m);
    cudaGetSymbolAddress((void**)&pu,  g_u);
    cudaGetSymbolAddress((void**)&phH, g_hH);
    cudaGetSymbolAddress((void**)&phL, g_hL);
    cudaGetSymbolAddress((void**)&psc, g_scr);

    static cudaStream_t s2 = nullptr;
    static cudaEvent_t evF = nullptr, evCSR = nullptr;
    if (!s2) {
        cudaStreamCreateWithFlags(&s2, cudaStreamNonBlocking);
        cudaEventCreateWithFlags(&evF,   cudaEventDisableTiming);
        cudaEventCreateWithFlags(&evCSR, cudaEventDisableTiming);
    }

    static bool attrs_set = false;
    if (!attrs_set) {
        cudaFuncSetAttribute(dual_gemm_wmma, cudaFuncAttributeMaxDynamicSharedMemorySize, GEMM_SMEM);
        cudaFuncSetAttribute(out_gemm_wmma,  cudaFuncAttributeMaxDynamicSharedMemorySize, OUT_SMEM);
        attrs_set = true;
    }

    int eb = (E + 255) / 256;
    int ab = (N * 32 + 255) / 256;

    // fork: CSR build on s2, concurrent with prep + gemm0
    cudaEventRecord(evF, 0);
    cudaStreamWaitEvent(s2, evF, 0);
    zero_kernel<<<148, 256, 0, s2>>>(ei, N);
    hist_kernel<<<eb, 256, 0, s2>>>(ei, E);
    scan_kernel<<<1, 1024, 0, s2>>>(N);
    scatter_kernel<<<eb, 256, 0, s2>>>(ei, ew, E);
    cudaEventRecord(evCSR, s2);

    prep_kernel<<<148, 256>>>(Wm0, Wu0, Wm1, Wu1, Wm2, Wu2, x, N);

    const float* bus[3] = {bu0, bu1, bu2};
    for (int l = 0; l < 3; l++) {
        const __nv_bfloat16* Whi = pW + (size_t)l * 2 * 256 * 128;
        const __nv_bfloat16* Wlo = Whi + 256 * 128;
        dual_gemm_wmma<<<148, 512, GEMM_SMEM>>>(phH, phL, Whi, Wlo, pm, pu, N);
        if (l == 0) cudaStreamWaitEvent(0, evCSR, 0);   // join CSR before first aggregate
        agg_tanh<<<ab, 256>>>(pm, pu, bus[l], phH, phL, N);
    }
    out_gemm_wmma<<<148, 256, OUT_SMEM>>>(phH, phL, Wout, bout, out, psc, N);
    (void)n_in; (void)out_size;
}

// round 15
// speedup vs baseline: 2.1240x; 2.1240x over previous
#include <cuda_runtime.h>
#include <cuda_bf16.h>
#include <cuda_fp16.h>
#include <mma.h>
#include <stdint.h>
#include <math.h>

using namespace nvcuda;

#define NMAX 50048   // 391 * 128, WMMA tile stores never OOB
#define EMAX 1000000

__device__ __nv_bfloat16 g_Wbf[3][2][256*128]; // [layer][hi/lo][c][k]
__device__ __half g_m[NMAX*128];               // fp16 messages
__device__ float  g_u[NMAX*128];
__device__ __nv_bfloat16 g_hH[NMAX*128];       // h (or x) hi part
__device__ __nv_bfloat16 g_hL[NMAX*128];       // h (or x) lo part
__device__ float  g_scr[NMAX*32];
__device__ int    g_is64;
__device__ int    g_cnt[NMAX];
__device__ int    g_off[NMAX + 1];
__device__ int    g_cur[NMAX];
__device__ int    g_src_sorted[EMAX];
__device__ float  g_w_sorted[EMAX];

// ================= prep: weights + x -> bf16 hi/lo =================
__global__ void prep_kernel(const float* __restrict__ Wm0, const float* __restrict__ Wu0,
                            const float* __restrict__ Wm1, const float* __restrict__ Wu1,
                            const float* __restrict__ Wm2, const float* __restrict__ Wu2,
                            const float* __restrict__ x, int N) {
    int idx = blockIdx.x * blockDim.x + threadIdx.x;
    const int wt = 3 * 256 * 128;
    for (int t = idx; t < wt; t += gridDim.x * blockDim.x) {
        int l = t / (256 * 128);
        int r = t % (256 * 128);
        int c = r / 128;
        int k = r % 128;
        const float* W;
        if (c < 128) W = (l == 0) ? Wm0 : (l == 1) ? Wm1 : Wm2;
        else         W = (l == 0) ? Wu0 : (l == 1) ? Wu1 : Wu2;
        float v = W[(c & 127) * 128 + k];
        __nv_bfloat16 hi = __float2bfloat16(v);
        __nv_bfloat16 lo = __float2bfloat16(v - __bfloat162float(hi));
        g_Wbf[l][0][c * 128 + k] = hi;
        g_Wbf[l][1][c * 128 + k] = lo;
    }
    int xt = N * 128 / 4;
    for (int t = idx; t < xt; t += gridDim.x * blockDim.x) {
        float4 v = ((const float4*)x)[t];
        union { unsigned short u[4]; uint2 q; } H, L;
        float vv[4] = {v.x, v.y, v.z, v.w};
        #pragma unroll
        for (int j = 0; j < 4; j++) {
            __nv_bfloat16 hv = __float2bfloat16(vv[j]);
            __nv_bfloat16 lv = __float2bfloat16(vv[j] - __bfloat162float(hv));
            H.u[j] = __bfloat16_as_ushort(hv);
            L.u[j] = __bfloat16_as_ushort(lv);
        }
        ((uint2*)g_hH)[t] = H.q;
        ((uint2*)g_hL)[t] = L.q;
    }
}

// ================= CSR build (forked stream) =================
__global__ void zero_kernel(const void* __restrict__ ei, int N) {
    int idx = blockIdx.x * blockDim.x + threadIdx.x;
    if (idx == 0) {
        const int* p = (const int*)ei;
        int is64 = 1;
        for (int i = 0; i < 32; i++) if (p[2*i + 1] != 0) { is64 = 0; break; }
        g_is64 = is64;
    }
    for (int t = idx; t < N; t += gridDim.x * blockDim.x) g_cnt[t] = 0;
}

__global__ void hist_kernel(const void* __restrict__ ei, int E) {
    int i = blockIdx.x * blockDim.x + threadIdx.x;
    if (i >= E) return;
    int dst = g_is64 ? (int)((const long long*)ei)[E + i] : ((const int*)ei)[E + i];
    atomicAdd(&g_cnt[dst], 1);
}

__global__ __launch_bounds__(1024) void scan_kernel(int N) {
    __shared__ int part[1024];
    int t = threadIdx.x;
    int chunk = (N + 1023) / 1024;
    int b = t * chunk;
    int e = min(b + chunk, N);
    int s = 0;
    for (int i = b; i < e; i++) s += g_cnt[i];
    part[t] = s;
    __syncthreads();
    for (int d = 1; d < 1024; d <<= 1) {
        int v = (t >= d) ? part[t - d] : 0;
        __syncthreads();
        part[t] += v;
        __syncthreads();
    }
    int run = (t == 0) ? 0 : part[t - 1];
    for (int i = b; i < e; i++) {
        int c = g_cnt[i];
        g_off[i] = run;
        g_cur[i] = run;
        run += c;
    }
    if (e == N && b <= N) g_off[N] = run;
}

__global__ void scatter_kernel(const void* __restrict__ ei, const float* __restrict__ ew, int E) {
    int i = blockIdx.x * blockDim.x + threadIdx.x;
    if (i >= E) return;
    int src, dst;
    if (g_is64) {
        const long long* p = (const long long*)ei;
        src = (int)p[i]; dst = (int)p[E + i];
    } else {
        const int* p = (const int*)ei;
        src = p[i]; dst = p[E + i];
    }
    int pos = atomicAdd(&g_cur[dst], 1);
    g_src_sorted[pos] = src;
    g_w_sorted[pos]   = ew[i];
}

// ================= WMMA dual GEMM (proven form: 256 thr, 8 warps, 1D tiling) =================
#define LDP 136
#define XS_H 0
#define XS_L (128*LDP*2)
#define WS_H (2*128*LDP*2)
#define WS_L (WS_H + 256*LDP*2)
#define G_EPI (WS_L + 256*LDP*2)
#define GEMM_SMEM (G_EPI + 8*256*4)

__global__ __launch_bounds__(256, 1) void dual_gemm_wmma(
    const __nv_bfloat16* __restrict__ aHg, const __nv_bfloat16* __restrict__ aLg,
    const __nv_bfloat16* __restrict__ Whi, const __nv_bfloat16* __restrict__ Wlo,
    __half* __restrict__ outm, float* __restrict__ outu, int N)
{
    extern __shared__ char sm[];
    __nv_bfloat16* xsH = (__nv_bfloat16*)(sm + XS_H);
    __nv_bfloat16* xsL = (__nv_bfloat16*)(sm + XS_L);
    __nv_bfloat16* wsH = (__nv_bfloat16*)(sm + WS_H);
    __nv_bfloat16* wsL = (__nv_bfloat16*)(sm + WS_L);
    int tid = threadIdx.x, warp = tid >> 5, lane = tid & 31;
    float* ep = (float*)(sm + G_EPI) + warp * 256;

    for (int i = tid; i < 256 * 16; i += 256) {
        int r = i >> 4, ch = i & 15;
        ((uint4*)(wsH + r * LDP))[ch] = ((const uint4*)(Whi + r * 128))[ch];
        ((uint4*)(wsL + r * LDP))[ch] = ((const uint4*)(Wlo + r * 128))[ch];
    }

    int ntiles = (N + 127) >> 7;

    for (int tile = blockIdx.x; tile < ntiles; tile += gridDim.x) {
        int row0 = tile << 7;
        __syncthreads();
        for (int i = tid; i < 2048; i += 256) {
            int r = i >> 4, ch = i & 15;
            size_t g = (size_t)(row0 + r) * 128;
            ((uint4*)(xsH + r * LDP))[ch] = ((const uint4*)(aHg + g))[ch];
            ((uint4*)(xsL + r * LDP))[ch] = ((const uint4*)(aLg + g))[ch];
        }
        __syncthreads();

        int gr0 = row0 + warp * 16;
        #pragma unroll
        for (int nc = 0; nc < 4; nc++) {
            wmma::fragment<wmma::accumulator, 16, 16, 16, float> acc[4];
            #pragma unroll
            for (int f = 0; f < 4; f++) wmma::fill_fragment(acc[f], 0.0f);

            #pragma unroll
            for (int pass = 0; pass < 3; pass++) {
                const __nv_bfloat16* A = (pass == 2) ? xsL : xsH;
                const __nv_bfloat16* B = (pass == 1) ? wsL : wsH;
                #pragma unroll
                for (int k = 0; k < 8; k++) {
                    wmma::fragment<wmma::matrix_a, 16, 16, 16, __nv_bfloat16, wmma::row_major> af;
                    wmma::load_matrix_sync(af, A + (warp * 16) * LDP + k * 16, LDP);
                    #pragma unroll
                    for (int f = 0; f < 4; f++) {
                        wmma::fragment<wmma::matrix_b, 16, 16, 16, __nv_bfloat16, wmma::col_major> bf;
                        wmma::load_matrix_sync(bf, B + (nc * 64 + f * 16) * LDP + k * 16, LDP);
                        wmma::mma_sync(acc[f], af, bf, acc[f]);
                    }
                }
            }
            #pragma unroll
            for (int f = 0; f < 4; f++) {
                int n0 = nc * 64 + f * 16;
                if (n0 < 128) {
                    wmma::store_matrix_sync(ep, acc[f], 16, wmma::mem_row_major);
                    __syncwarp();
                    int row = lane >> 1, c0 = (lane & 1) * 8;
                    const float* s = ep + row * 16 + c0;
                    union { __half h[8]; uint4 q; } o;
                    #pragma unroll
                    for (int j = 0; j < 8; j++) o.h[j] = __float2half_rn(s[j]);
                    *(uint4*)(outm + (size_t)(gr0 + row) * 128 + n0 + c0) = o.q;
                    __syncwarp();
                } else {
                    wmma::store_matrix_sync(outu + (size_t)gr0 * 128 + (n0 - 128),
                                            acc[f], 128, wmma::mem_row_major);
                }
            }
        }
    }
}

// ================= fused CSR aggregate (fp16 gather, 8-edge unroll) + bias + fast tanh =================
__device__ __forceinline__ float fast_tanh(float x) {
    float e = __expf(2.0f * x);
    return 1.0f - 2.0f / (e + 1.0f);
}

__global__ __launch_bounds__(256) void agg_tanh(
    const __half* __restrict__ m, const float* __restrict__ u,
    const float* __restrict__ bu,
    __nv_bfloat16* __restrict__ hH, __nv_bfloat16* __restrict__ hL, int N)
{
    int node = (blockIdx.x * blockDim.x + threadIdx.x) >> 5;
    int lane = threadIdx.x & 31;
    if (node >= N) return;
    int b = g_off[node], e = g_off[node + 1];

    float4 bb = *(const float4*)(bu + lane*4);
    float4 uu = *(const float4*)(u + (size_t)node*128 + lane*4);
    float4 acc = make_float4(uu.x + bb.x, uu.y + bb.y, uu.z + bb.z, uu.w + bb.w);

    int i = b;
    for (; i + 8 <= e; i += 8) {
        int   s[8];
        float w[8];
        #pragma unroll
        for (int j = 0; j < 8; j++) { s[j] = g_src_sorted[i + j]; w[j] = g_w_sorted[i + j]; }
        uint2 r[8];
        #pragma unroll
        for (int j = 0; j < 8; j++) r[j] = *(const uint2*)(m + (size_t)s[j]*128 + lane*4);
        #pragma unroll
        for (int j = 0; j < 8; j++) {
            float2 a = __half22float2(*(__half2*)&r[j].x);
            float2 c = __half22float2(*(__half2*)&r[j].y);
            acc.x = fmaf(w[j], a.x, acc.x);
            acc.y = fmaf(w[j], a.y, acc.y);
            acc.z = fmaf(w[j], c.x, acc.z);
            acc.w = fmaf(w[j], c.y, acc.w);
        }
    }
    for (; i < e; i++) {
        int   s = g_src_sorted[i];
        float w = g_w_sorted[i];
        uint2 r = *(const uint2*)(m + (size_t)s*128 + lane*4);
        float2 a = __half22float2(*(__half2*)&r.x), c = __half22float2(*(__half2*)&r.y);
        acc.x = fmaf(w, a.x, acc.x);
        acc.y = fmaf(w, a.y, acc.y);
        acc.z = fmaf(w, c.x, acc.z);
        acc.w = fmaf(w, c.y, acc.w);
    }
    float v[4] = {fast_tanh(acc.x), fast_tanh(acc.y), fast_tanh(acc.z), fast_tanh(acc.w)};
    union { unsigned short us[4]; uint2 q; } H, L;
    #pragma unroll
    for (int j = 0; j < 4; j++) {
        __nv_bfloat16 hv = __float2bfloat16(v[j]);
        __nv_bfloat16 lv = __float2bfloat16(v[j] - __bfloat162float(hv));
        H.us[j] = __bfloat16_as_ushort(hv);
        L.us[j] = __bfloat16_as_ushort(lv);
    }
    *(uint2*)(hH + (size_t)node*128 + lane*4) = H.q;
    *(uint2*)(hL + (size_t)node*128 + lane*4) = L.q;
}

// ================= WMMA output GEMM: out = h @ Wout.T + bout (C=32) =================
#define OLDP 136
#define OA_H 0
#define OA_L (128*OLDP*2)
#define OW_H (2*128*OLDP*2)
#define OW_L (OW_H + 32*OLDP*2)
#define OBIAS (OW_L + 32*OLDP*2)
#define OUT_SMEM (OBIAS + 16*40*4)

__global__ __launch_bounds__(256, 1) void out_gemm_wmma(
    const __nv_bfloat16* __restrict__ aHg, const __nv_bfloat16* __restrict__ aLg,
    const float* __restrict__ Wout,
    const float* __restrict__ bout, float* __restrict__ out,
    float* __restrict__ scratch, int N)
{
    extern __shared__ char sm[];
    __nv_bfloat16* aH = (__nv_bfloat16*)(sm + OA_H);
    __nv_bfloat16* aL = (__nv_bfloat16*)(sm + OA_L);
    __nv_bfloat16* wH = (__nv_bfloat16*)(sm + OW_H);
    __nv_bfloat16* wL = (__nv_bfloat16*)(sm + OW_L);
    float* bs = (float*)(sm + OBIAS);
    int tid = threadIdx.x, warp = tid >> 5, lane = tid & 31;

    for (int i = tid; i < 32 * 16; i += 256) {
        int r = i >> 4, ch = i & 15;
        float4 a = *(const float4*)(Wout + r * 128 + ch * 8);
        float4 b = *(const float4*)(Wout + r * 128 + ch * 8 + 4);
        float v[8] = {a.x, a.y, a.z, a.w, b.x, b.y, b.z, b.w};
        union { unsigned short u[8]; uint4 q; } H, L;
        #pragma unroll
        for (int j = 0; j < 8; j++) {
            __nv_bfloat16 hv = __float2bfloat16(v[j]);
            __nv_bfloat16 lv = __float2bfloat16(v[j] - __bfloat162float(hv));
            H.u[j] = __bfloat16_as_ushort(hv);
            L.u[j] = __bfloat16_as_ushort(lv);
        }
        *(uint4*)(wH + r * OLDP + ch * 8) = H.q;
        *(uint4*)(wL + r * OLDP + ch * 8) = L.q;
    }
    for (int i = tid; i < 16 * 40; i += 256) {
        int c = i % 40;
        bs[i] = (c < 32) ? bout[c] : 0.f;
    }

    int ntiles = (N + 127) >> 7;
    for (int tile = blockIdx.x; tile < ntiles; tile += gridDim.x) {
        int row0 = tile << 7;
        __syncthreads();
        for (int i = tid; i < 2048; i += 256) {
            int r = i >> 4, ch = i & 15;
            size_t g = (size_t)(row0 + r) * 128;
            ((uint4*)(aH + r * OLDP))[ch] = ((const uint4*)(aHg + g))[ch];
            ((uint4*)(aL + r * OLDP))[ch] = ((const uint4*)(aLg + g))[ch];
        }
        __syncthreads();

        wmma::fragment<wmma::accumulator, 16, 16, 16, float> acc[2];
        #pragma unroll
        for (int f = 0; f < 2; f++)
            wmma::load_matrix_sync(acc[f], bs + f * 16, 40, wmma::mem_row_major);

        #pragma unroll
        for (int pass = 0; pass < 3; pass++) {
            const __nv_bfloat16* A = (pass == 2) ? aL : aH;
            const __nv_bfloat16* B = (pass == 1) ? wL : wH;
            #pragma unroll
            for (int k = 0; k < 8; k++) {
                wmma::fragment<wmma::matrix_a, 16, 16, 16, __nv_bfloat16, wmma::row_major> af;
                wmma::load_matrix_sync(af, A + (warp * 16) * OLDP + k * 16, OLDP);
                #pragma unroll
                for (int f = 0; f < 2; f++) {
                    wmma::fragment<wmma::matrix_b, 16, 16, 16, __nv_bfloat16, wmma::col_major> bf;
                    wmma::load_matrix_sync(bf, B + (f * 16) * OLDP + k * 16, OLDP);
                    wmma::mma_sync(acc[f], af, bf, acc[f]);
                }
            }
        }
        int gr0 = row0 + warp * 16;
        if (gr0 + 16 <= N) {
            wmma::store_matrix_sync(out + (size_t)gr0 * 32,      acc[0], 32, wmma::mem_row_major);
            wmma::store_matrix_sync(out + (size_t)gr0 * 32 + 16, acc[1], 32, wmma::mem_row_major);
        } else if (gr0 < N) {
            float* sc = scratch + (size_t)gr0 * 32;
            wmma::store_matrix_sync(sc,      acc[0], 32, wmma::mem_row_major);
            wmma::store_matrix_sync(sc + 16, acc[1], 32, wmma::mem_row_major);
            __syncwarp();
            for (int r = 0; r < 16; r++) {
                int gr = gr0 + r;
                if (gr < N) out[(size_t)gr * 32 + lane] = sc[r * 32 + lane];
            }
        }
    }
}

extern "C" void kernel_launch(void* const* d_in, const int* in_sizes, int n_in,
                              void* d_out, int out_size) {
    const float* x    = (const float*)d_in[0];
    const void*  ei   = d_in[1];
    const float* ew   = (const float*)d_in[2];
    const float* Wm0  = (const float*)d_in[3];
    const float* Wu0  = (const float*)d_in[4];
    const float* bu0  = (const float*)d_in[5];
    const float* Wm1  = (const float*)d_in[6];
    const float* Wu1  = (const float*)d_in[7];
    const float* bu1  = (const float*)d_in[8];
    const float* Wm2  = (const float*)d_in[9];
    const float* Wu2  = (const float*)d_in[10];
    const float* bu2  = (const float*)d_in[11];
    const float* Wout = (const float*)d_in[12];
    const float* bout = (const float*)d_in[13];
    float* out = (float*)d_out;

    int N = in_sizes[0] / 128;
    int E = in_sizes[2];

    __nv_bfloat16 *pW, *phH, *phL;
    __half* pm;
    float *pu, *psc;
    cudaGetSymbolAddress((void**)&pW,  g_Wbf);
    cudaGetSymbolAddress((void**)&pm,  g_m);
    cudaGetSymbolAddress((void**)&pu,  g_u);
    cudaGetSymbolAddress((void**)&phH, g_hH);
    cudaGetSymbolAddress((void**)&phL, g_hL);
    cudaGetSymbolAddress((void**)&psc, g_scr);

    static cudaStream_t s2 = nullptr;
    static cudaEvent_t evF = nullptr, evCSR = nullptr;
    if (!s2) {
        cudaStreamCreateWithFlags(&s2, cudaStreamNonBlocking);
        cudaEventCreateWithFlags(&evF,   cudaEventDisableTiming);
        cudaEventCreateWithFlags(&evCSR, cudaEventDisableTiming);
    }

    static bool attrs_set = false;
    if (!attrs_set) {
        cudaFuncSetAttribute(dual_gemm_wmma, cudaFuncAttributeMaxDynamicSharedMemorySize, GEMM_SMEM);
        cudaFuncSetAttribute(out_gemm_wmma,  cudaFuncAttributeMaxDynamicSharedMemorySize, OUT_SMEM);
        attrs_set = true;
    }

    int eb = (E + 255) / 256;
    int ab = (N * 32 + 255) / 256;

    // fork: CSR build on s2, concurrent with prep + gemm0
    cudaEventRecord(evF, 0);
    cudaStreamWaitEvent(s2, evF, 0);
    zero_kernel<<<148, 256, 0, s2>>>(ei, N);
    hist_kernel<<<eb, 256, 0, s2>>>(ei, E);
    scan_kernel<<<1, 1024, 0, s2>>>(N);
    scatter_kernel<<<eb, 256, 0, s2>>>(ei, ew, E);
    cudaEventRecord(evCSR, s2);

    prep_kernel<<<148, 256>>>(Wm0, Wu0, Wm1, Wu1, Wm2, Wu2, x, N);

    const float* bus[3] = {bu0, bu1, bu2};
    for (int l = 0; l < 3; l++) {
        const __nv_bfloat16* Whi = pW + (size_t)l * 2 * 256 * 128;
        const __nv_bfloat16* Wlo = Whi + 256 * 128;
        dual_gemm_wmma<<<148, 256, GEMM_SMEM>>>(phH, phL, Whi, Wlo, pm, pu, N);
        if (l == 0) cudaStreamWaitEvent(0, evCSR, 0);   // join CSR before first aggregate
        agg_tanh<<<ab, 256>>>(pm, pu, bus[l], phH, phL, N);
    }
    out_gemm_wmma<<<148, 256, OUT_SMEM>>>(phH, phL, Wout, bout, out, psc, N);
    (void)n_in; (void)out_size;
}